// round 2
// baseline (speedup 1.0000x reference)
#include <cuda_runtime.h>
#include <cstdint>

// Problem constants
#define NROWS 65536
#define DDIM  1024
#define KC    256

// ---------------- device scratch (no allocations allowed) ----------------
__device__ float g_U[(size_t)NROWS * KC];
__device__ float g_V[(size_t)NROWS * KC];
__device__ float g_Z[(size_t)NROWS * KC];
__device__ float g_Hpart[64 * KC * KC];   // 64 n-splits of H = Z^T V
__device__ float g_H[KC * KC];            // H[j][k] = sum_n Z[n,j] V[n,k]
__device__ float g_cspU[256 * KC];
__device__ float g_cspV[256 * KC];
__device__ float g_D;

// ---------------- helpers ----------------
__device__ __forceinline__ unsigned f2tf(float f) {
    unsigned u;
    asm("cvt.rna.tf32.f32 %0, %1;" : "=r"(u) : "f"(f));
    return u;
}
__device__ __forceinline__ void cpa16(float* s, const float* g) {
    unsigned sa = (unsigned)__cvta_generic_to_shared(s);
    asm volatile("cp.async.cg.shared.global [%0], [%1], 16;" :: "r"(sa), "l"(g));
}
__device__ __forceinline__ void cpcommit() { asm volatile("cp.async.commit_group;"); }
template <int N> __device__ __forceinline__ void cpwait() {
    asm volatile("cp.async.wait_group %0;" :: "n"(N));
}
__device__ __forceinline__ void mma8(float* c, const unsigned* a, const unsigned* b) {
    asm volatile(
        "mma.sync.aligned.m16n8k8.row.col.f32.tf32.tf32.f32 "
        "{%0,%1,%2,%3},{%4,%5,%6,%7},{%8,%9},{%0,%1,%2,%3};"
        : "+f"(c[0]), "+f"(c[1]), "+f"(c[2]), "+f"(c[3])
        : "r"(a[0]), "r"(a[1]), "r"(a[2]), "r"(a[3]), "r"(b[0]), "r"(b[1]));
}

// ---------------- C = A * B^T  (A: [M,KA] row-major, B: [NB,KA] row-major) ----------------
// EPI=0: GEMM1 (bias+relu, scatter U/V/Z/T).  EPI=1: res = U*H^T * D -> out[:,0:256]
template <int KA, int EPI>
__global__ __launch_bounds__(256)
void gemm_nt(const float* __restrict__ Ain, const float* __restrict__ Bin,
             const float* __restrict__ bias, float* __restrict__ out) {
    extern __shared__ float sm[];
    const int AS = 128 * 36;
    float* sA[2] = { sm, sm + AS };
    float* sB[2] = { sm + 2 * AS, sm + 3 * AS };

    const float* A = (EPI == 1) ? g_U : Ain;
    const float* B = (EPI == 1) ? g_H : Bin;

    int m0 = blockIdx.y * 128, n0 = blockIdx.x * 128;
    int tid = threadIdx.x;
    int warp = tid >> 5, lane = tid & 31, g = lane >> 2, tg = lane & 3;
    int wm = (warp >> 2) * 64, wn = (warp & 3) * 32;

    float acc[4][4][4];
#pragma unroll
    for (int i = 0; i < 4; i++)
#pragma unroll
        for (int j = 0; j < 4; j++)
#pragma unroll
            for (int c = 0; c < 4; c++) acc[i][j][c] = 0.f;

    const int NK = KA / 32;
    auto load_stage = [&](int s, int kt) {
        int k0 = kt * 32;
#pragma unroll
        for (int i = 0; i < 4; i++) {
            int vi = tid + i * 256;
            int row = vi >> 3, kv = (vi & 7) * 4;
            cpa16(sA[s] + row * 36 + kv, A + (size_t)(m0 + row) * KA + k0 + kv);
            cpa16(sB[s] + row * 36 + kv, B + (size_t)(n0 + row) * KA + k0 + kv);
        }
        cpcommit();
    };

    load_stage(0, 0);
    int buf = 0;
    for (int kt = 0; kt < NK; kt++) {
        if (kt + 1 < NK) { load_stage(buf ^ 1, kt + 1); cpwait<1>(); }
        else             { cpwait<0>(); }
        __syncthreads();
        const float* cA = sA[buf];
        const float* cB = sB[buf];
#pragma unroll
        for (int kk = 0; kk < 4; kk++) {
            unsigned af[4][4], bf[4][2];
#pragma unroll
            for (int mt = 0; mt < 4; mt++) {
                const float* p = cA + (wm + mt * 16 + g) * 36 + kk * 8 + tg;
                af[mt][0] = f2tf(p[0]);
                af[mt][1] = f2tf(p[8 * 36]);
                af[mt][2] = f2tf(p[4]);
                af[mt][3] = f2tf(p[8 * 36 + 4]);
            }
#pragma unroll
            for (int nt = 0; nt < 4; nt++) {
                const float* p = cB + (wn + nt * 8 + g) * 36 + kk * 8 + tg;
                bf[nt][0] = f2tf(p[0]);
                bf[nt][1] = f2tf(p[4]);
            }
#pragma unroll
            for (int mt = 0; mt < 4; mt++)
#pragma unroll
                for (int nt = 0; nt < 4; nt++)
                    mma8(acc[mt][nt], af[mt], bf[nt]);
        }
        __syncthreads();
        buf ^= 1;
    }

    // epilogue
    float Dscale = (EPI == 1) ? g_D : 1.f;
#pragma unroll
    for (int mt = 0; mt < 4; mt++)
#pragma unroll
        for (int nt = 0; nt < 4; nt++)
#pragma unroll
            for (int c = 0; c < 4; c++) {
                int rl = wm + mt * 16 + g + ((c >= 2) ? 8 : 0);
                int cl = wn + nt * 8 + tg * 2 + (c & 1);
                int gr = m0 + rl, gc = n0 + cl;
                float v = acc[mt][nt][c];
                if (EPI == 0) {
                    v += __ldg(bias + gc);
                    v = fmaxf(v, 0.f);
                    if (gc < 768) {
                        float* dst = (gc < 256) ? g_U : ((gc < 512) ? g_V : g_Z);
                        dst[(size_t)gr * KC + (gc & 255)] = v;
                    } else {
                        out[(size_t)gr * 512 + 256 + (gc - 768)] = v;
                    }
                } else {
                    out[(size_t)gr * 512 + gc] = v * Dscale;
                }
            }
}

// ---------------- H partials: Hpart[z][j][k] = sum over n-chunk of Z[n,j]*V[n,k] ----------------
__global__ __launch_bounds__(256)
void gemm_tn() {
    extern __shared__ float sm[];
    const int TS = 32 * 132;
    float* sZ[2] = { sm, sm + TS };
    float* sV[2] = { sm + 2 * TS, sm + 3 * TS };

    int k0 = blockIdx.x * 128;   // cols of H (V columns)
    int j0 = blockIdx.y * 128;   // rows of H (Z columns)
    int nb = blockIdx.z * 1024;  // n-chunk base
    int tid = threadIdx.x;
    int warp = tid >> 5, lane = tid & 31, g = lane >> 2, tg = lane & 3;
    int wm = (warp >> 2) * 64, wn = (warp & 3) * 32;

    float acc[4][4][4];
#pragma unroll
    for (int i = 0; i < 4; i++)
#pragma unroll
        for (int j = 0; j < 4; j++)
#pragma unroll
            for (int c = 0; c < 4; c++) acc[i][j][c] = 0.f;

    auto load_stage = [&](int s, int it) {
        int r0 = nb + it * 32;
#pragma unroll
        for (int i = 0; i < 4; i++) {
            int vi = tid + i * 256;
            int row = vi >> 5, cv = (vi & 31) * 4;
            cpa16(sZ[s] + row * 132 + cv, g_Z + (size_t)(r0 + row) * KC + j0 + cv);
            cpa16(sV[s] + row * 132 + cv, g_V + (size_t)(r0 + row) * KC + k0 + cv);
        }
        cpcommit();
    };

    const int NK = 32;  // 1024 rows / 32
    load_stage(0, 0);
    int buf = 0;
    for (int kt = 0; kt < NK; kt++) {
        if (kt + 1 < NK) { load_stage(buf ^ 1, kt + 1); cpwait<1>(); }
        else             { cpwait<0>(); }
        __syncthreads();
        const float* cZ = sZ[buf];
        const float* cV = sV[buf];
#pragma unroll
        for (int kk = 0; kk < 4; kk++) {
            int kb = kk * 8 + tg;
            unsigned af[4][4], bf[4][2];
#pragma unroll
            for (int mt = 0; mt < 4; mt++) {
                const float* p = cZ + kb * 132 + wm + mt * 16 + g;
                af[mt][0] = f2tf(p[0]);
                af[mt][1] = f2tf(p[8]);
                af[mt][2] = f2tf(p[4 * 132]);
                af[mt][3] = f2tf(p[4 * 132 + 8]);
            }
#pragma unroll
            for (int nt = 0; nt < 4; nt++) {
                const float* p = cV + kb * 132 + wn + nt * 8 + g;
                bf[nt][0] = f2tf(p[0]);
                bf[nt][1] = f2tf(p[4 * 132]);
            }
#pragma unroll
            for (int mt = 0; mt < 4; mt++)
#pragma unroll
                for (int nt = 0; nt < 4; nt++)
                    mma8(acc[mt][nt], af[mt], bf[nt]);
        }
        __syncthreads();
        buf ^= 1;
    }

    float* dst = g_Hpart + (size_t)blockIdx.z * (KC * KC);
#pragma unroll
    for (int mt = 0; mt < 4; mt++)
#pragma unroll
        for (int nt = 0; nt < 4; nt++)
#pragma unroll
            for (int c = 0; c < 4; c++) {
                int rl = wm + mt * 16 + g + ((c >= 2) ? 8 : 0);
                int cl = wn + nt * 8 + tg * 2 + (c & 1);
                dst[(j0 + rl) * KC + (k0 + cl)] = acc[mt][nt][c];
            }
}

// ---------------- column-sum partials of U and V ----------------
__global__ void colsum_k() {
    const float* src = (blockIdx.y == 0) ? g_U : g_V;
    float* dst = (blockIdx.y == 0) ? g_cspU : g_cspV;
    int j = threadIdx.x;
    int r0 = blockIdx.x * 256;
    float s = 0.f;
    for (int r = 0; r < 256; r++) s += src[(size_t)(r0 + r) * KC + j];
    dst[blockIdx.x * KC + j] = s;
}

// ---------------- scalar D ----------------
__global__ void scalar_k() {
    int j = threadIdx.x;
    float su = 0.f, sv = 0.f;
    for (int b = 0; b < 256; b++) {
        su += g_cspU[b * KC + j];
        sv += g_cspV[b * KC + j];
    }
    float p = su * sv;
#pragma unroll
    for (int o = 16; o > 0; o >>= 1) p += __shfl_xor_sync(0xffffffffu, p, o);
    __shared__ float red[8];
    if ((j & 31) == 0) red[j >> 5] = p;
    __syncthreads();
    if (j == 0) {
        float t = 0.f;
        for (int w = 0; w < 8; w++) t += red[w];
        g_D = 1.f / (t / (float)NROWS + 1e-6f);
    }
}

// ---------------- reduce H partials ----------------
__global__ void reduceH_k() {
    int i = blockIdx.x * 256 + threadIdx.x;
    float s = 0.f;
    for (int p = 0; p < 64; p++) s += g_Hpart[(size_t)p * (KC * KC) + i];
    g_H[i] = s;
}

// ---------------- launcher ----------------
extern "C" void kernel_launch(void* const* d_in, const int* in_sizes, int n_in,
                              void* d_out, int out_size) {
    const float* x = (const float*)d_in[0];
    const float* W = (const float*)d_in[1];
    const float* b = (const float*)d_in[2];
    float* out = (float*)d_out;

    const int SM_NT = 4 * 128 * 36 * 4;   // 73728 B
    const int SM_TN = 4 * 32 * 132 * 4;   // 67584 B
    cudaFuncSetAttribute(gemm_nt<1024, 0>, cudaFuncAttributeMaxDynamicSharedMemorySize, SM_NT);
    cudaFuncSetAttribute(gemm_nt<256, 1>,  cudaFuncAttributeMaxDynamicSharedMemorySize, SM_NT);
    cudaFuncSetAttribute(gemm_tn,          cudaFuncAttributeMaxDynamicSharedMemorySize, SM_TN);

    // 1) tmp = relu(x W^T + b): U/V/Z to scratch, T -> out[:,256:512]
    gemm_nt<1024, 0><<<dim3(8, 512), 256, SM_NT>>>(x, W, b, out);
    // 2) column sums of U and V (partials)
    colsum_k<<<dim3(256, 2), 256>>>();
    // 3) H = Z^T V partials over 64 n-splits
    gemm_tn<<<dim3(2, 2, 64), 256, SM_TN>>>();
    // 4) D scalar
    scalar_k<<<1, 256>>>();
    // 5) reduce H partials (deterministic order)
    reduceH_k<<<256, 256>>>();
    // 6) res = U * H^T * D -> out[:,0:256]
    gemm_nt<256, 1><<<dim3(2, 512), 256, SM_NT>>>(nullptr, nullptr, nullptr, out);
}

// round 7
// speedup vs baseline: 1.4717x; 1.4717x over previous
#include <cuda_runtime.h>
#include <cstdint>

// Problem constants
#define NROWS 65536
#define DDIM  1024
#define KC    256

// ---------------- device scratch (no allocations allowed) ----------------
__device__ float g_U[(size_t)NROWS * KC];
__device__ float g_V[(size_t)NROWS * KC];
__device__ float g_Z[(size_t)NROWS * KC];
__device__ float g_Hpart[64 * KC * KC];   // 64 n-splits of H = Z^T V
__device__ float g_H[KC * KC];            // H[j][k] = sum_n Z[n,j] V[n,k]
__device__ float g_cspU[256 * KC];
__device__ float g_cspV[256 * KC];
__device__ float g_D;

// ---------------- helpers ----------------
__device__ __forceinline__ unsigned f2tf(float f) {
    unsigned u;
    asm("cvt.rna.tf32.f32 %0, %1;" : "=r"(u) : "f"(f));
    return u;
}
__device__ __forceinline__ void cpa16(float* s, const float* g) {
    unsigned sa = (unsigned)__cvta_generic_to_shared(s);
    asm volatile("cp.async.cg.shared.global [%0], [%1], 16;" :: "r"(sa), "l"(g));
}
__device__ __forceinline__ void cpcommit() { asm volatile("cp.async.commit_group;"); }
template <int N> __device__ __forceinline__ void cpwait() {
    asm volatile("cp.async.wait_group %0;" :: "n"(N));
}
__device__ __forceinline__ void mma8(float* c, const unsigned* a, const unsigned* b) {
    asm volatile(
        "mma.sync.aligned.m16n8k8.row.col.f32.tf32.tf32.f32 "
        "{%0,%1,%2,%3},{%4,%5,%6,%7},{%8,%9},{%0,%1,%2,%3};"
        : "+f"(c[0]), "+f"(c[1]), "+f"(c[2]), "+f"(c[3])
        : "r"(a[0]), "r"(a[1]), "r"(a[2]), "r"(a[3]), "r"(b[0]), "r"(b[1]));
}

// ================= NT GEMM: C[M,N] = A[M,KA] * B[N,KA]^T =================
// CTA 128x128, 4 warps (2x2), warp tile 64x64. 3-stage cp.async pipeline,
// one __syncthreads per K-chunk, fragment double-buffering in the kk loop.
// EPI=0: bias+relu; bx 0..5 scatter to U/V/Z, bx 6..7 -> out[:,256:512].
// EPI=1: res = U * H^T * g_D -> out[:, 0:256].
template <int KA, int EPI>
__global__ __launch_bounds__(128, 2)
void gemm_nt(const float* __restrict__ Ain, const float* __restrict__ Bin,
             const float* __restrict__ bias, float* __restrict__ out) {
    extern __shared__ float sm[];
    const int ST = 128 * 36;                 // floats per operand per stage

    const float* A = (EPI == 1) ? g_U : Ain;
    const float* B = (EPI == 1) ? g_H : Bin;

    const int m0 = blockIdx.y * 128, n0 = blockIdx.x * 128;
    const int tid = threadIdx.x;
    const int warp = tid >> 5, lane = tid & 31, g = lane >> 2, tg = lane & 3;
    const int wm = (warp >> 1) * 64, wn = (warp & 1) * 64;

    float acc[4][8][4];
#pragma unroll
    for (int i = 0; i < 4; i++)
#pragma unroll
        for (int j = 0; j < 8; j++)
#pragma unroll
            for (int c = 0; c < 4; c++) acc[i][j][c] = 0.f;

    const int NK = KA / 32;

    auto load_stage = [&](int s) {
        float* sA = sm + (s % 3) * (2 * ST);
        float* sB = sA + ST;
        const int k0 = s * 32;
#pragma unroll
        for (int i = 0; i < 8; i++) {
            int idx = tid + i * 128;
            int row = idx >> 3, kv = (idx & 7) * 4;
            cpa16(sA + row * 36 + kv, A + (size_t)(m0 + row) * KA + k0 + kv);
            cpa16(sB + row * 36 + kv, B + (size_t)(n0 + row) * KA + k0 + kv);
        }
        cpcommit();
    };

    load_stage(0);
    load_stage(1);

    for (int kt = 0; kt < NK; kt++) {
        if (kt + 1 < NK) cpwait<1>(); else cpwait<0>();
        __syncthreads();
        // buffer (kt+2)%3 held stage kt-1; all readers passed the barrier above.
        if (kt + 2 < NK) load_stage(kt + 2);

        const float* cA = sm + (kt % 3) * (2 * ST);
        const float* cB = cA + ST;

        unsigned af[2][4][4], bf[2][8][2];
        auto ldfA = [&](int kk, unsigned (*dst)[4]) {
#pragma unroll
            for (int mt = 0; mt < 4; mt++) {
                const float* p = cA + (wm + mt * 16 + g) * 36 + kk * 8 + tg;
                dst[mt][0] = f2tf(p[0]);
                dst[mt][1] = f2tf(p[8 * 36]);
                dst[mt][2] = f2tf(p[4]);
                dst[mt][3] = f2tf(p[8 * 36 + 4]);
            }
        };
        auto ldfB = [&](int kk, unsigned (*dst)[2]) {
#pragma unroll
            for (int nt = 0; nt < 8; nt++) {
                const float* p = cB + (wn + nt * 8 + g) * 36 + kk * 8 + tg;
                dst[nt][0] = f2tf(p[0]);
                dst[nt][1] = f2tf(p[4]);
            }
        };

        ldfA(0, af[0]);
        ldfB(0, bf[0]);
#pragma unroll
        for (int kk = 0; kk < 4; kk++) {
            int cur = kk & 1;
            if (kk < 3) {            // prefetch next kk's fragments
                ldfA(kk + 1, af[cur ^ 1]);
                ldfB(kk + 1, bf[cur ^ 1]);
            }
#pragma unroll
            for (int mt = 0; mt < 4; mt++)
#pragma unroll
                for (int nt = 0; nt < 8; nt++)
                    mma8(acc[mt][nt], af[cur][mt], bf[cur][nt]);
        }
    }

    // ---------------- epilogue (float2 stores, no smem) ----------------
    const float Dscale = (EPI == 1) ? g_D : 1.f;
#pragma unroll
    for (int mt = 0; mt < 4; mt++) {
#pragma unroll
        for (int nt = 0; nt < 8; nt++) {
            int cl = wn + nt * 8 + tg * 2;          // col in [0,128)
            int r0 = wm + mt * 16 + g;              // rows r0, r0+8
            float2 v01 = make_float2(acc[mt][nt][0], acc[mt][nt][1]);
            float2 v23 = make_float2(acc[mt][nt][2], acc[mt][nt][3]);
            if (EPI == 0) {
                float2 bb = *(const float2*)(bias + n0 + cl);
                v01.x = fmaxf(v01.x + bb.x, 0.f); v01.y = fmaxf(v01.y + bb.y, 0.f);
                v23.x = fmaxf(v23.x + bb.x, 0.f); v23.y = fmaxf(v23.y + bb.y, 0.f);
                int bx = blockIdx.x;                // 8 n-blocks of 128
                int lc = (bx & 1) * 128 + cl;       // col within 256-seg
                if (bx < 6) {
                    float* dst = (bx < 2) ? g_U : ((bx < 4) ? g_V : g_Z);
                    *(float2*)(dst + (size_t)(m0 + r0) * KC + lc) = v01;
                    *(float2*)(dst + (size_t)(m0 + r0 + 8) * KC + lc) = v23;
                } else {
                    *(float2*)(out + (size_t)(m0 + r0) * 512 + 256 + lc) = v01;
                    *(float2*)(out + (size_t)(m0 + r0 + 8) * 512 + 256 + lc) = v23;
                }
            } else {
                v01.x *= Dscale; v01.y *= Dscale; v23.x *= Dscale; v23.y *= Dscale;
                int gc = n0 + cl;
                *(float2*)(out + (size_t)(m0 + r0) * 512 + gc) = v01;
                *(float2*)(out + (size_t)(m0 + r0 + 8) * 512 + gc) = v23;
            }
        }
    }
}

// ---------------- H partials: Hpart[z][j][k] = sum over n-chunk of Z[n,j]*V[n,k] ----------------
__global__ __launch_bounds__(256)
void gemm_tn() {
    extern __shared__ float sm[];
    const int TS = 32 * 132;
    float* sZ[2] = { sm, sm + TS };
    float* sV[2] = { sm + 2 * TS, sm + 3 * TS };

    int k0 = blockIdx.x * 128;
    int j0 = blockIdx.y * 128;
    int nb = blockIdx.z * 1024;
    int tid = threadIdx.x;
    int warp = tid >> 5, lane = tid & 31, g = lane >> 2, tg = lane & 3;
    int wm = (warp >> 2) * 64, wn = (warp & 3) * 32;

    float acc[4][4][4];
#pragma unroll
    for (int i = 0; i < 4; i++)
#pragma unroll
        for (int j = 0; j < 4; j++)
#pragma unroll
            for (int c = 0; c < 4; c++) acc[i][j][c] = 0.f;

    auto load_stage = [&](int s, int it) {
        int r0 = nb + it * 32;
#pragma unroll
        for (int i = 0; i < 4; i++) {
            int vi = tid + i * 256;
            int row = vi >> 5, cv = (vi & 31) * 4;
            cpa16(sZ[s] + row * 132 + cv, g_Z + (size_t)(r0 + row) * KC + j0 + cv);
            cpa16(sV[s] + row * 132 + cv, g_V + (size_t)(r0 + row) * KC + k0 + cv);
        }
        cpcommit();
    };

    const int NK = 32;
    load_stage(0, 0);
    int buf = 0;
    for (int kt = 0; kt < NK; kt++) {
        if (kt + 1 < NK) { load_stage(buf ^ 1, kt + 1); cpwait<1>(); }
        else             { cpwait<0>(); }
        __syncthreads();
        const float* cZ = sZ[buf];
        const float* cV = sV[buf];
#pragma unroll
        for (int kk = 0; kk < 4; kk++) {
            int kb = kk * 8 + tg;
            unsigned af[4][4], bf[4][2];
#pragma unroll
            for (int mt2 = 0; mt2 < 4; mt2++) {
                const float* p = cZ + kb * 132 + wm + mt2 * 16 + g;
                af[mt2][0] = f2tf(p[0]);
                af[mt2][1] = f2tf(p[8]);
                af[mt2][2] = f2tf(p[4 * 132]);
                af[mt2][3] = f2tf(p[4 * 132 + 8]);
            }
#pragma unroll
            for (int nt = 0; nt < 4; nt++) {
                const float* p = cV + kb * 132 + wn + nt * 8 + g;
                bf[nt][0] = f2tf(p[0]);
                bf[nt][1] = f2tf(p[4 * 132]);
            }
#pragma unroll
            for (int mt2 = 0; mt2 < 4; mt2++)
#pragma unroll
                for (int nt = 0; nt < 4; nt++)
                    mma8(acc[mt2][nt], af[mt2], bf[nt]);
        }
        __syncthreads();
        buf ^= 1;
    }

    float* dst = g_Hpart + (size_t)blockIdx.z * (KC * KC);
#pragma unroll
    for (int mt2 = 0; mt2 < 4; mt2++)
#pragma unroll
        for (int nt = 0; nt < 4; nt++)
#pragma unroll
            for (int c = 0; c < 4; c++) {
                int rl = wm + mt2 * 16 + g + ((c >= 2) ? 8 : 0);
                int cl = wn + nt * 8 + tg * 2 + (c & 1);
                dst[(j0 + rl) * KC + (k0 + cl)] = acc[mt2][nt][c];
            }
}

// ---------------- column-sum partials of U and V ----------------
__global__ void colsum_k() {
    const float* src = (blockIdx.y == 0) ? g_U : g_V;
    float* dst = (blockIdx.y == 0) ? g_cspU : g_cspV;
    int j = threadIdx.x;
    int r0 = blockIdx.x * 256;
    float s = 0.f;
    for (int r = 0; r < 256; r++) s += src[(size_t)(r0 + r) * KC + j];
    dst[blockIdx.x * KC + j] = s;
}

// ---------------- scalar D ----------------
__global__ void scalar_k() {
    int j = threadIdx.x;
    float su = 0.f, sv = 0.f;
    for (int b = 0; b < 256; b++) {
        su += g_cspU[b * KC + j];
        sv += g_cspV[b * KC + j];
    }
    float p = su * sv;
#pragma unroll
    for (int o = 16; o > 0; o >>= 1) p += __shfl_xor_sync(0xffffffffu, p, o);
    __shared__ float red[8];
    if ((j & 31) == 0) red[j >> 5] = p;
    __syncthreads();
    if (j == 0) {
        float t = 0.f;
        for (int w = 0; w < 8; w++) t += red[w];
        g_D = 1.f / (t / (float)NROWS + 1e-6f);
    }
}

// ---------------- reduce H partials ----------------
__global__ void reduceH_k() {
    int i = blockIdx.x * 256 + threadIdx.x;
    float s = 0.f;
    for (int p = 0; p < 64; p++) s += g_Hpart[(size_t)p * (KC * KC) + i];
    g_H[i] = s;
}

// ---------------- launcher ----------------
extern "C" void kernel_launch(void* const* d_in, const int* in_sizes, int n_in,
                              void* d_out, int out_size) {
    const float* x = (const float*)d_in[0];
    const float* W = (const float*)d_in[1];
    const float* b = (const float*)d_in[2];
    float* out = (float*)d_out;

    const int SM_NT = 3 * 2 * 128 * 36 * 4;   // 110592 B (3 stages x A+B)
    const int SM_TN = 4 * 32 * 132 * 4;       // 67584 B
    cudaFuncSetAttribute(gemm_nt<1024, 0>, cudaFuncAttributeMaxDynamicSharedMemorySize, SM_NT);
    cudaFuncSetAttribute(gemm_nt<256, 1>,  cudaFuncAttributeMaxDynamicSharedMemorySize, SM_NT);
    cudaFuncSetAttribute(gemm_tn,          cudaFuncAttributeMaxDynamicSharedMemorySize, SM_TN);

    // 1) tmp = relu(x W^T + b): bx 0..5 -> U/V/Z scratch, bx 6..7 -> out[:,256:512]
    gemm_nt<1024, 0><<<dim3(8, 512), 128, SM_NT>>>(x, W, b, out);
    // 2) column sums of U and V (partials)
    colsum_k<<<dim3(256, 2), 256>>>();
    // 3) H = Z^T V partials over 64 n-splits
    gemm_tn<<<dim3(2, 2, 64), 256, SM_TN>>>();
    // 4) D scalar
    scalar_k<<<1, 256>>>();
    // 5) reduce H partials (deterministic order)
    reduceH_k<<<256, 256>>>();
    // 6) res = U * H^T * D -> out[:,0:256]  (N=256 -> grid.x = 2, NOT 8)
    gemm_nt<256, 1><<<dim3(2, 512), 128, SM_NT>>>(nullptr, nullptr, nullptr, out);
}

// round 8
// speedup vs baseline: 1.5505x; 1.0535x over previous
#include <cuda_runtime.h>
#include <cstdint>

// Problem constants
#define NROWS 65536
#define DDIM  1024
#define KC    256

// ---------------- device scratch (no allocations allowed) ----------------
__device__ float g_U[(size_t)NROWS * KC];
__device__ float g_V[(size_t)NROWS * KC];
__device__ float g_Z[(size_t)NROWS * KC];
__device__ float g_Wr[(size_t)DDIM * DDIM];   // rna-tf32-rounded W
__device__ float g_Hpart[64 * KC * KC];
__device__ float g_H[KC * KC];
__device__ float g_cspU[256 * KC];
__device__ float g_cspV[256 * KC];
__device__ float g_pdot[KC];
__device__ float g_D;

// ---------------- helpers ----------------
__device__ __forceinline__ unsigned f2tf(float f) {
    unsigned u;
    asm("cvt.rna.tf32.f32 %0, %1;" : "=r"(u) : "f"(f));
    return u;
}
__device__ __forceinline__ float f2tf_f(float f) { return __uint_as_float(f2tf(f)); }
__device__ __forceinline__ void cpa16(float* s, const float* g) {
    unsigned sa = (unsigned)__cvta_generic_to_shared(s);
    asm volatile("cp.async.cg.shared.global [%0], [%1], 16;" :: "r"(sa), "l"(g));
}
__device__ __forceinline__ void cpcommit() { asm volatile("cp.async.commit_group;"); }
template <int N> __device__ __forceinline__ void cpwait() {
    asm volatile("cp.async.wait_group %0;" :: "n"(N));
}
__device__ __forceinline__ void mma8(float* c, const unsigned* a, const unsigned* b) {
    asm volatile(
        "mma.sync.aligned.m16n8k8.row.col.f32.tf32.tf32.f32 "
        "{%0,%1,%2,%3},{%4,%5,%6,%7},{%8,%9},{%0,%1,%2,%3};"
        : "+f"(c[0]), "+f"(c[1]), "+f"(c[2]), "+f"(c[3])
        : "r"(a[0]), "r"(a[1]), "r"(a[2]), "r"(a[3]), "r"(b[0]), "r"(b[1]));
}

// ---------------- prepass: W -> rna-tf32-rounded g_Wr ----------------
__global__ void round_W_k(const float* __restrict__ W) {
    int i = (blockIdx.x * 256 + threadIdx.x) * 4;
    float4 v = *(const float4*)(W + i);
    v.x = f2tf_f(v.x); v.y = f2tf_f(v.y); v.z = f2tf_f(v.z); v.w = f2tf_f(v.w);
    *(float4*)(g_Wr + i) = v;
}
__global__ void dummy_k() {}

// ================= NT GEMM: C[M,N] = A[M,KA] * B[N,KA]^T =================
// CTA tile 128(M) x 256(N), 8 warps (2x4), warp tile 64x64. 3-stage cp.async,
// one __syncthreads per K-chunk, fragment double-buffering across kk.
// CVT_A=1: apply cvt.rna.tf32 to A fragments (A not pre-rounded).
// B fragments always loaded raw (pre-rounded operands).
// EPI=0: bias+relu; bx 0/1/2 -> U/V/Z (stored tf32-rounded), bx 3 -> out[:,256:512].
// EPI=1: res = U * H^T * g_D -> out[:, 0:256].
template <int KA, int CVT_A, int EPI>
__global__ __launch_bounds__(256, 1)
void gemm_nt(const float* __restrict__ Ain, const float* __restrict__ bias,
             float* __restrict__ out) {
    extern __shared__ float sm[];
    const int SA = 128 * 36;                 // A floats per stage
    const int SB = 256 * 36;                 // B floats per stage
    const int ST = SA + SB;

    const float* A = (EPI == 1) ? g_U : Ain;
    const float* B = (EPI == 1) ? g_H : g_Wr;

    const int m0 = blockIdx.y * 128, n0 = blockIdx.x * 256;
    const int tid = threadIdx.x;
    const int warp = tid >> 5, lane = tid & 31, g = lane >> 2, tg = lane & 3;
    const int wm = (warp >> 2) * 64, wn = (warp & 3) * 64;

    float acc[4][8][4];
#pragma unroll
    for (int i = 0; i < 4; i++)
#pragma unroll
        for (int j = 0; j < 8; j++)
#pragma unroll
            for (int c = 0; c < 4; c++) acc[i][j][c] = 0.f;

    const int NK = KA / 32;

    auto load_stage = [&](int s) {
        float* sA = sm + (s % 3) * ST;
        float* sB = sA + SA;
        const int k0 = s * 32;
#pragma unroll
        for (int i = 0; i < 4; i++) {        // A: 128 rows x 32k
            int idx = tid + i * 256;
            int row = idx >> 3, kv = (idx & 7) * 4;
            cpa16(sA + row * 36 + kv, A + (size_t)(m0 + row) * KA + k0 + kv);
        }
#pragma unroll
        for (int i = 0; i < 8; i++) {        // B: 256 rows x 32k
            int idx = tid + i * 256;
            int row = idx >> 3, kv = (idx & 7) * 4;
            cpa16(sB + row * 36 + kv, B + (size_t)(n0 + row) * KA + k0 + kv);
        }
        cpcommit();
    };

    load_stage(0);
    load_stage(1);

    for (int kt = 0; kt < NK; kt++) {
        if (kt + 1 < NK) cpwait<1>(); else cpwait<0>();
        __syncthreads();
        // buffer (kt+2)%3 was last read in iter kt-1; all readers passed the barrier.
        if (kt + 2 < NK) load_stage(kt + 2);

        const float* cA = sm + (kt % 3) * ST;
        const float* cB = cA + SA;

        unsigned af[2][4][4], bf[2][8][2];
        auto ldfA = [&](int kk, unsigned (*dst)[4]) {
#pragma unroll
            for (int mt = 0; mt < 4; mt++) {
                const float* p = cA + (wm + mt * 16 + g) * 36 + kk * 8 + tg;
                if (CVT_A) {
                    dst[mt][0] = f2tf(p[0]);
                    dst[mt][1] = f2tf(p[8 * 36]);
                    dst[mt][2] = f2tf(p[4]);
                    dst[mt][3] = f2tf(p[8 * 36 + 4]);
                } else {
                    dst[mt][0] = __float_as_uint(p[0]);
                    dst[mt][1] = __float_as_uint(p[8 * 36]);
                    dst[mt][2] = __float_as_uint(p[4]);
                    dst[mt][3] = __float_as_uint(p[8 * 36 + 4]);
                }
            }
        };
        auto ldfB = [&](int kk, unsigned (*dst)[2]) {
#pragma unroll
            for (int nt = 0; nt < 8; nt++) {
                const float* p = cB + (wn + nt * 8 + g) * 36 + kk * 8 + tg;
                dst[nt][0] = __float_as_uint(p[0]);
                dst[nt][1] = __float_as_uint(p[4]);
            }
        };

        ldfA(0, af[0]);
        ldfB(0, bf[0]);
#pragma unroll
        for (int kk = 0; kk < 4; kk++) {
            int cur = kk & 1;
            if (kk < 3) {
                ldfA(kk + 1, af[cur ^ 1]);
                ldfB(kk + 1, bf[cur ^ 1]);
            }
#pragma unroll
            for (int mt = 0; mt < 4; mt++)
#pragma unroll
                for (int nt = 0; nt < 8; nt++)
                    mma8(acc[mt][nt], af[cur][mt], bf[cur][nt]);
        }
    }

    // ---------------- epilogue ----------------
    const float Dscale = (EPI == 1) ? g_D : 1.f;
#pragma unroll
    for (int mt = 0; mt < 4; mt++) {
#pragma unroll
        for (int nt = 0; nt < 8; nt++) {
            int cl = wn + nt * 8 + tg * 2;          // col in [0,256)
            int r0 = wm + mt * 16 + g;              // rows r0, r0+8
            float2 v01 = make_float2(acc[mt][nt][0], acc[mt][nt][1]);
            float2 v23 = make_float2(acc[mt][nt][2], acc[mt][nt][3]);
            if (EPI == 0) {
                float2 bb = *(const float2*)(bias + n0 + cl);
                v01.x = fmaxf(v01.x + bb.x, 0.f); v01.y = fmaxf(v01.y + bb.y, 0.f);
                v23.x = fmaxf(v23.x + bb.x, 0.f); v23.y = fmaxf(v23.y + bb.y, 0.f);
                int bx = blockIdx.x;                // 4 n-blocks of 256
                if (bx < 3) {
                    // scratch operands: store tf32-rounded so consumers skip cvt
                    v01.x = f2tf_f(v01.x); v01.y = f2tf_f(v01.y);
                    v23.x = f2tf_f(v23.x); v23.y = f2tf_f(v23.y);
                    float* dst = (bx == 0) ? g_U : ((bx == 1) ? g_V : g_Z);
                    *(float2*)(dst + (size_t)(m0 + r0) * KC + cl) = v01;
                    *(float2*)(dst + (size_t)(m0 + r0 + 8) * KC + cl) = v23;
                } else {
                    *(float2*)(out + (size_t)(m0 + r0) * 512 + 256 + cl) = v01;
                    *(float2*)(out + (size_t)(m0 + r0 + 8) * 512 + 256 + cl) = v23;
                }
            } else {
                v01.x *= Dscale; v01.y *= Dscale; v23.x *= Dscale; v23.y *= Dscale;
                *(float2*)(out + (size_t)(m0 + r0) * 512 + cl) = v01;
                *(float2*)(out + (size_t)(m0 + r0 + 8) * 512 + cl) = v23;
            }
        }
    }
}

// ---------------- H partials: Hpart[z][j][k] = sum over n-chunk of Z[n,j]*V[n,k] ----------------
__global__ __launch_bounds__(256)
void gemm_tn() {
    extern __shared__ float sm[];
    const int TS = 32 * 132;
    float* sZ[2] = { sm, sm + TS };
    float* sV[2] = { sm + 2 * TS, sm + 3 * TS };

    int k0 = blockIdx.x * 128;
    int j0 = blockIdx.y * 128;
    int nb = blockIdx.z * 1024;
    int tid = threadIdx.x;
    int warp = tid >> 5, lane = tid & 31, g = lane >> 2, tg = lane & 3;
    int wm = (warp >> 2) * 64, wn = (warp & 3) * 32;

    float acc[4][4][4];
#pragma unroll
    for (int i = 0; i < 4; i++)
#pragma unroll
        for (int j = 0; j < 4; j++)
#pragma unroll
            for (int c = 0; c < 4; c++) acc[i][j][c] = 0.f;

    auto load_stage = [&](int s, int it) {
        int r0 = nb + it * 32;
#pragma unroll
        for (int i = 0; i < 4; i++) {
            int vi = tid + i * 256;
            int row = vi >> 5, cv = (vi & 31) * 4;
            cpa16(sZ[s] + row * 132 + cv, g_Z + (size_t)(r0 + row) * KC + j0 + cv);
            cpa16(sV[s] + row * 132 + cv, g_V + (size_t)(r0 + row) * KC + k0 + cv);
        }
        cpcommit();
    };

    const int NK = 32;
    load_stage(0, 0);
    int buf = 0;
    for (int kt = 0; kt < NK; kt++) {
        if (kt + 1 < NK) { load_stage(buf ^ 1, kt + 1); cpwait<1>(); }
        else             { cpwait<0>(); }
        __syncthreads();
        const float* cZ = sZ[buf];
        const float* cV = sV[buf];
#pragma unroll
        for (int kk = 0; kk < 4; kk++) {
            int kb = kk * 8 + tg;
            unsigned af[4][4], bf[4][2];
#pragma unroll
            for (int mt2 = 0; mt2 < 4; mt2++) {
                const float* p = cZ + kb * 132 + wm + mt2 * 16 + g;
                af[mt2][0] = __float_as_uint(p[0]);
                af[mt2][1] = __float_as_uint(p[8]);
                af[mt2][2] = __float_as_uint(p[4 * 132]);
                af[mt2][3] = __float_as_uint(p[4 * 132 + 8]);
            }
#pragma unroll
            for (int nt = 0; nt < 4; nt++) {
                const float* p = cV + kb * 132 + wn + nt * 8 + g;
                bf[nt][0] = __float_as_uint(p[0]);
                bf[nt][1] = __float_as_uint(p[4 * 132]);
            }
#pragma unroll
            for (int mt2 = 0; mt2 < 4; mt2++)
#pragma unroll
                for (int nt = 0; nt < 4; nt++)
                    mma8(acc[mt2][nt], af[mt2], bf[nt]);
        }
        __syncthreads();
        buf ^= 1;
    }

    float* dst = g_Hpart + (size_t)blockIdx.z * (KC * KC);
#pragma unroll
    for (int mt2 = 0; mt2 < 4; mt2++)
#pragma unroll
        for (int nt = 0; nt < 4; nt++)
#pragma unroll
            for (int c = 0; c < 4; c++) {
                int rl = wm + mt2 * 16 + g + ((c >= 2) ? 8 : 0);
                int cl = wn + nt * 8 + tg * 2 + (c & 1);
                dst[(j0 + rl) * KC + (k0 + cl)] = acc[mt2][nt][c];
            }
}

// ---------------- column-sum partials of U and V ----------------
__global__ void colsum_k() {
    const float* src = (blockIdx.y == 0) ? g_U : g_V;
    float* dst = (blockIdx.y == 0) ? g_cspU : g_cspV;
    int j = threadIdx.x;
    int r0 = blockIdx.x * 256;
    float s = 0.f;
    for (int r = 0; r < 256; r++) s += src[(size_t)(r0 + r) * KC + j];
    dst[blockIdx.x * KC + j] = s;
}

// ---------------- per-column dot partial: pdot[j] = su_j * sv_j ----------------
__global__ void sumpart_k() {
    int j = blockIdx.x;          // column
    int t = threadIdx.x;         // partial index
    float u = g_cspU[t * KC + j];
    float v = g_cspV[t * KC + j];
#pragma unroll
    for (int o = 16; o > 0; o >>= 1) {
        u += __shfl_xor_sync(0xffffffffu, u, o);
        v += __shfl_xor_sync(0xffffffffu, v, o);
    }
    __shared__ float ru[8], rv[8];
    if ((t & 31) == 0) { ru[t >> 5] = u; rv[t >> 5] = v; }
    __syncthreads();
    if (t == 0) {
        float su = 0.f, sv = 0.f;
        for (int w = 0; w < 8; w++) { su += ru[w]; sv += rv[w]; }
        g_pdot[j] = su * sv;
    }
}

// ---------------- scalar D ----------------
__global__ void scalar_k() {
    int t = threadIdx.x;
    float p = g_pdot[t * 8] + g_pdot[t * 8 + 1] + g_pdot[t * 8 + 2] + g_pdot[t * 8 + 3]
            + g_pdot[t * 8 + 4] + g_pdot[t * 8 + 5] + g_pdot[t * 8 + 6] + g_pdot[t * 8 + 7];
#pragma unroll
    for (int o = 16; o > 0; o >>= 1) p += __shfl_xor_sync(0xffffffffu, p, o);
    if (t == 0) g_D = 1.f / (p / (float)NROWS + 1e-6f);
}

// ---------------- reduce H partials (store tf32-rounded) ----------------
__global__ void reduceH_k() {
    int i = blockIdx.x * 256 + threadIdx.x;
    float s = 0.f;
    for (int p = 0; p < 64; p++) s += g_Hpart[(size_t)p * (KC * KC) + i];
    g_H[i] = f2tf_f(s);
}

// ---------------- launcher ----------------
extern "C" void kernel_launch(void* const* d_in, const int* in_sizes, int n_in,
                              void* d_out, int out_size) {
    const float* x = (const float*)d_in[0];
    const float* W = (const float*)d_in[1];
    const float* b = (const float*)d_in[2];
    float* out = (float*)d_out;

    const int SM_NT = 3 * (128 + 256) * 36 * 4;  // 165888 B
    const int SM_TN = 4 * 32 * 132 * 4;          // 67584 B
    cudaFuncSetAttribute(gemm_nt<1024, 1, 0>, cudaFuncAttributeMaxDynamicSharedMemorySize, SM_NT);
    cudaFuncSetAttribute(gemm_nt<256, 0, 1>,  cudaFuncAttributeMaxDynamicSharedMemorySize, SM_NT);
    cudaFuncSetAttribute(gemm_tn,             cudaFuncAttributeMaxDynamicSharedMemorySize, SM_TN);

    // 0) prepass + ncu alignment: gemm1 lands at global launch index 5 (-s 5)
    round_W_k<<<1024, 256>>>(W);
    dummy_k<<<1, 32>>>();
    dummy_k<<<1, 32>>>();
    // 1) tmp = relu(x W^T + b): bx 0/1/2 -> U/V/Z (tf32-rounded), bx 3 -> out[:,256:512]
    gemm_nt<1024, 1, 0><<<dim3(4, 512), 256, SM_NT>>>(x, b, out);
    // 2) column sums of U and V (partials)
    colsum_k<<<dim3(256, 2), 256>>>();
    // 3) per-column dot partials
    sumpart_k<<<256, 256>>>();
    // 4) H = Z^T V partials over 64 n-splits
    gemm_tn<<<dim3(2, 2, 64), 256, SM_TN>>>();
    // 5) D scalar
    scalar_k<<<1, 32>>>();
    // 6) reduce H partials (deterministic order, tf32-rounded)
    reduceH_k<<<256, 256>>>();
    // 7) res = U * H^T * D -> out[:,0:256]
    gemm_nt<256, 0, 1><<<dim3(1, 512), 256, SM_NT>>>(nullptr, nullptr, out);
}